// round 4
// baseline (speedup 1.0000x reference)
#include <cuda_runtime.h>
#include <cuda_fp16.h>
#include <cstdint>

#define MBLK 64
#define PDIM 256
#define BATCH 4096
#define ROWSTRIDE 16384          // MBLK*PDIM floats per batch row

#define TILE_M 128               // batch rows per CTA
#define TILE_N 256               // full output block width
#define BK 32                    // K floats per pipeline chunk
#define NCHUNK 24                // 3 segments * 256/32
#define NSTAGE 3

#define ASTRIDE 36               // padded fp32 row stride (floats)
#define SA_FLOATS (TILE_M * ASTRIDE)            // 4608
#define SB_FLOATS (TILE_N * ASTRIDE)            // 9216
#define STAGE_FLOATS (SA_FLOATS + SB_FLOATS)    // 13824
#define SMEM_BYTES (STAGE_FLOATS * 4 * NSTAGE)  // 165888

__device__ __forceinline__ uint32_t smem_u32(const void* p) {
    uint32_t a;
    asm("{ .reg .u64 t; cvta.to.shared.u64 t, %1; cvt.u32.u64 %0, t; }" : "=r"(a) : "l"(p));
    return a;
}

__device__ __forceinline__ void cp16(uint32_t dst, const void* src) {
    asm volatile("cp.async.cg.shared.global [%0], [%1], 16;\n" :: "r"(dst), "l"(src));
}
__device__ __forceinline__ void cp_commit() {
    asm volatile("cp.async.commit_group;\n" ::: "memory");
}
template <int N>
__device__ __forceinline__ void cp_wait() {
    asm volatile("cp.async.wait_group %0;\n" :: "n"(N) : "memory");
}

// fp16 m16n8k16, fp32 accumulate
__device__ __forceinline__ void mma16(float* c,
                                      uint32_t a0, uint32_t a1, uint32_t a2, uint32_t a3,
                                      uint32_t b0, uint32_t b1) {
    asm volatile(
        "mma.sync.aligned.m16n8k16.row.col.f32.f16.f16.f32 "
        "{%0,%1,%2,%3}, {%4,%5,%6,%7}, {%8,%9}, {%0,%1,%2,%3};\n"
        : "+f"(c[0]), "+f"(c[1]), "+f"(c[2]), "+f"(c[3])
        : "r"(a0), "r"(a1), "r"(a2), "r"(a3), "r"(b0), "r"(b1));
}

__device__ __forceinline__ uint32_t h2(const float* p) {
    float2 v = *reinterpret_cast<const float2*>(p);
    __half2 h = __floats2half2_rn(v.x, v.y);
    return *reinterpret_cast<uint32_t*>(&h);
}

__device__ __forceinline__ const float* seg_w(int s, int i,
                                              const float* Wd, const float* Wu,
                                              const float* Wl, const float* Wtr,
                                              const float* Wbl, int& j) {
    if (s == 0) { j = i;            return Wd + (size_t)i * (PDIM * PDIM); }
    if (s == 1) { j = (i + 1) & 63; return (i < 63) ? Wu + (size_t)i * (PDIM * PDIM) : Wbl; }
    j = (i + 63) & 63;              return (i > 0) ? Wl + (size_t)(i - 1) * (PDIM * PDIM) : Wtr;
}

__global__ void __launch_bounds__(512, 1)
bxdiag_f16_kernel(const float* __restrict__ x,
                  const float* __restrict__ Wd,
                  const float* __restrict__ Wu,
                  const float* __restrict__ Wl,
                  const float* __restrict__ Wtr,
                  const float* __restrict__ Wbl,
                  float* __restrict__ out)
{
    extern __shared__ __align__(128) float smem[];
    const uint32_t sbase = smem_u32(smem);

    const int tid = threadIdx.x;
    const int wid = tid >> 5;
    const int lid = tid & 31;
    const int wm  = wid & 3;       // 0..3 : 32-row quarter
    const int wn  = wid >> 2;      // 0..3 : 64-col quarter
    const int bt  = blockIdx.x;    // batch tile 0..31
    const int i   = blockIdx.y;    // output block 0..63
    const int row0 = bt * TILE_M;

    // ---- stage issuer: 512 threads, 2 A-chunks + 4 B-chunks of 16B each ----
    auto issue_stage = [&](int c) {
        const int s  = c >> 3;
        const int k0 = (c & 7) * BK;
        int j;
        const float* W = seg_w(s, i, Wd, Wu, Wl, Wtr, Wbl, j);
        const float* xsrc = x + (size_t)row0 * ROWSTRIDE + j * PDIM + k0;
        const float* wsrc = W + k0;
        const uint32_t ab = sbase + (uint32_t)((c % NSTAGE) * STAGE_FLOATS) * 4u;
        const uint32_t bb = ab + SA_FLOATS * 4u;
        #pragma unroll
        for (int it = 0; it < 2; ++it) {           // A: 128 rows x 8 chunks
            const int ch = tid + it * 512;
            const int r = ch >> 3, cc = ch & 7;
            cp16(ab + (uint32_t)(r * ASTRIDE + cc * 4) * 4u,
                 xsrc + (size_t)r * ROWSTRIDE + cc * 4);
        }
        #pragma unroll
        for (int it = 0; it < 4; ++it) {           // B: 256 rows x 8 chunks
            const int ch = tid + it * 512;
            const int r = ch >> 3, cc = ch & 7;
            cp16(bb + (uint32_t)(r * ASTRIDE + cc * 4) * 4u,
                 wsrc + r * PDIM + cc * 4);
        }
    };

    float acc[2][8][4];
    #pragma unroll
    for (int mt = 0; mt < 2; ++mt)
        #pragma unroll
        for (int nt = 0; nt < 8; ++nt)
            #pragma unroll
            for (int q = 0; q < 4; ++q)
                acc[mt][nt][q] = 0.0f;

    issue_stage(0); cp_commit();
    issue_stage(1); cp_commit();

    const int g  = lid >> 2;   // 0..7
    const int tg = lid & 3;    // 0..3

    #pragma unroll 1
    for (int c = 0; c < NCHUNK; ++c) {
        if (c + 2 < NCHUNK) issue_stage(c + 2);
        cp_commit();
        cp_wait<2>();          // chunk c resident
        __syncthreads();

        const float* sAb = smem + (c % NSTAGE) * STAGE_FLOATS;
        const float* sBb = sAb + SA_FLOATS;
        // A rows: wm*32 + mt*16 + g (+8);  B rows(n): wn*64 + nt*8 + g
        const float* arow = sAb + (wm * 32 + g) * ASTRIDE + 2 * tg;
        const float* brow = sBb + (wn * 64 + g) * ASTRIDE + 2 * tg;

        #pragma unroll
        for (int k16 = 0; k16 < BK / 16; ++k16) {
            const float* ap = arow + k16 * 16;
            const float* bp = brow + k16 * 16;
            uint32_t a[2][4], b[8][2];
            #pragma unroll
            for (int mt = 0; mt < 2; ++mt) {
                a[mt][0] = h2(ap + (mt * 16)     * ASTRIDE);
                a[mt][1] = h2(ap + (mt * 16 + 8) * ASTRIDE);
                a[mt][2] = h2(ap + (mt * 16)     * ASTRIDE + 8);
                a[mt][3] = h2(ap + (mt * 16 + 8) * ASTRIDE + 8);
            }
            #pragma unroll
            for (int nt = 0; nt < 8; ++nt) {
                b[nt][0] = h2(bp + (nt * 8) * ASTRIDE);
                b[nt][1] = h2(bp + (nt * 8) * ASTRIDE + 8);
            }
            #pragma unroll
            for (int mt = 0; mt < 2; ++mt)
                #pragma unroll
                for (int nt = 0; nt < 8; ++nt)
                    mma16(acc[mt][nt], a[mt][0], a[mt][1], a[mt][2], a[mt][3],
                          b[nt][0], b[nt][1]);
        }
        __syncthreads();
    }

    // ---- epilogue ----
    float* ob = out + (size_t)row0 * ROWSTRIDE + i * PDIM;
    #pragma unroll
    for (int mt = 0; mt < 2; ++mt) {
        #pragma unroll
        for (int nt = 0; nt < 8; ++nt) {
            const int r0 = wm * 32 + mt * 16 + g;
            const int cc = wn * 64 + nt * 8 + tg * 2;
            float2 v0 = make_float2(acc[mt][nt][0], acc[mt][nt][1]);
            float2 v1 = make_float2(acc[mt][nt][2], acc[mt][nt][3]);
            *reinterpret_cast<float2*>(ob + (size_t)r0 * ROWSTRIDE + cc) = v0;
            *reinterpret_cast<float2*>(ob + (size_t)(r0 + 8) * ROWSTRIDE + cc) = v1;
        }
    }
}

extern "C" void kernel_launch(void* const* d_in, const int* in_sizes, int n_in,
                              void* d_out, int out_size)
{
    const float* x   = (const float*)d_in[0];
    const float* Wd  = (const float*)d_in[1];
    const float* Wu  = (const float*)d_in[2];
    const float* Wl  = (const float*)d_in[3];
    const float* Wtr = (const float*)d_in[4];
    const float* Wbl = (const float*)d_in[5];
    float* out = (float*)d_out;

    cudaFuncSetAttribute(bxdiag_f16_kernel,
                         cudaFuncAttributeMaxDynamicSharedMemorySize, SMEM_BYTES);
    dim3 grid(BATCH / TILE_M, MBLK);   // 32 x 64 = 2048 CTAs
    bxdiag_f16_kernel<<<grid, 512, SMEM_BYTES>>>(x, Wd, Wu, Wl, Wtr, Wbl, out);
}

// round 5
// speedup vs baseline: 1.5770x; 1.5770x over previous
#include <cuda_runtime.h>
#include <cuda_fp16.h>
#include <cstdint>

#define MBLK 64
#define PDIM 256
#define BATCH 4096
#define ROWSTRIDE 16384          // MBLK*PDIM floats per batch row

#define TILE_M 128
#define TILE_N 256
#define BK 32
#define NCHUNK 24                // 3 segments * 256/32

// fp32 staging: 2 stages, each A(128x32f)+B(256x32f) = 48KB
#define STG_BYTES 49152
#define STG_A_FLOATS (TILE_M * BK)           // 4096
// fp16 operand buffers: 80B row stride (conflict-free ldmatrix)
#define HROW 80
#define FA_OFF (2 * STG_BYTES)               // 98304
#define FB_OFF (FA_OFF + TILE_M * HROW)      // +10240
#define SMEM_BYTES (FB_OFF + TILE_N * HROW)  // 129024

__device__ __forceinline__ uint32_t smem_u32(const void* p) {
    uint32_t a;
    asm("{ .reg .u64 t; cvta.to.shared.u64 t, %1; cvt.u32.u64 %0, t; }" : "=r"(a) : "l"(p));
    return a;
}
__device__ __forceinline__ void cp16(uint32_t dst, const void* src) {
    asm volatile("cp.async.cg.shared.global [%0], [%1], 16;\n" :: "r"(dst), "l"(src));
}
__device__ __forceinline__ void cp_commit() {
    asm volatile("cp.async.commit_group;\n" ::: "memory");
}
template <int N>
__device__ __forceinline__ void cp_wait() {
    asm volatile("cp.async.wait_group %0;\n" :: "n"(N) : "memory");
}
__device__ __forceinline__ void ldsm4(uint32_t* r, uint32_t addr) {
    asm volatile("ldmatrix.sync.aligned.m8n8.x4.shared.b16 {%0,%1,%2,%3}, [%4];\n"
                 : "=r"(r[0]), "=r"(r[1]), "=r"(r[2]), "=r"(r[3]) : "r"(addr));
}
__device__ __forceinline__ void mma16(float* c,
                                      uint32_t a0, uint32_t a1, uint32_t a2, uint32_t a3,
                                      uint32_t b0, uint32_t b1) {
    asm volatile(
        "mma.sync.aligned.m16n8k16.row.col.f32.f16.f16.f32 "
        "{%0,%1,%2,%3}, {%4,%5,%6,%7}, {%8,%9}, {%0,%1,%2,%3};\n"
        : "+f"(c[0]), "+f"(c[1]), "+f"(c[2]), "+f"(c[3])
        : "r"(a0), "r"(a1), "r"(a2), "r"(a3), "r"(b0), "r"(b1));
}

__device__ __forceinline__ const float* seg_w(int s, int i,
                                              const float* Wd, const float* Wu,
                                              const float* Wl, const float* Wtr,
                                              const float* Wbl, int& j) {
    if (s == 0) { j = i;            return Wd + (size_t)i * (PDIM * PDIM); }
    if (s == 1) { j = (i + 1) & 63; return (i < 63) ? Wu + (size_t)i * (PDIM * PDIM) : Wbl; }
    j = (i + 63) & 63;              return (i > 0) ? Wl + (size_t)(i - 1) * (PDIM * PDIM) : Wtr;
}

__global__ void __launch_bounds__(256, 1)
bxdiag_ldsm_kernel(const float* __restrict__ x,
                   const float* __restrict__ Wd,
                   const float* __restrict__ Wu,
                   const float* __restrict__ Wl,
                   const float* __restrict__ Wtr,
                   const float* __restrict__ Wbl,
                   float* __restrict__ out)
{
    extern __shared__ __align__(128) float smem[];
    const uint32_t sbase = smem_u32(smem);

    const int tid = threadIdx.x;
    const int wid = tid >> 5;
    const int lid = tid & 31;
    const int wm  = wid & 1;       // 64-row half
    const int wn  = wid >> 1;      // 64-col quarter
    const int bt  = blockIdx.x;
    const int i   = blockIdx.y;
    const int row0 = bt * TILE_M;

    // ---- cp.async stage issuer (fp32, linear rows) ----
    auto issue_stage = [&](int c) {
        const int s  = c >> 3;
        const int k0 = (c & 7) * BK;
        int j;
        const float* W = seg_w(s, i, Wd, Wu, Wl, Wtr, Wbl, j);
        const float* xsrc = x + (size_t)row0 * ROWSTRIDE + j * PDIM + k0;
        const float* wsrc = W + k0;
        const uint32_t ab = sbase + (uint32_t)((c & 1) * STG_BYTES);
        const uint32_t bb = ab + STG_A_FLOATS * 4u;
        #pragma unroll
        for (int it = 0; it < 4; ++it) {           // A: 128 rows x 8 x 16B
            const int ch = tid + it * 256;
            const int r = ch >> 3, cc = ch & 7;
            cp16(ab + (uint32_t)(r * BK + cc * 4) * 4u,
                 xsrc + (size_t)r * ROWSTRIDE + cc * 4);
        }
        #pragma unroll
        for (int it = 0; it < 8; ++it) {           // B: 256 rows x 8 x 16B
            const int ch = tid + it * 256;
            const int r = ch >> 3, cc = ch & 7;
            cp16(bb + (uint32_t)(r * BK + cc * 4) * 4u,
                 wsrc + r * PDIM + cc * 4);
        }
    };

    float acc[4][8][4];
    #pragma unroll
    for (int mt = 0; mt < 4; ++mt)
        #pragma unroll
        for (int nt = 0; nt < 8; ++nt)
            #pragma unroll
            for (int q = 0; q < 4; ++q)
                acc[mt][nt][q] = 0.0f;

    issue_stage(0); cp_commit();
    issue_stage(1); cp_commit();

    // ldmatrix per-lane address components
    const int sub   = lid >> 3;                 // 0..3
    const int rowoff = ((sub & 1) << 3) + (lid & 7);
    const int koff   = (sub >> 1) << 3;         // 0 or 8
    const uint32_t fa = sbase + FA_OFF;
    const uint32_t fb = sbase + FB_OFF;

    #pragma unroll 1
    for (int c = 0; c < NCHUNK; ++c) {
        cp_wait<1>();
        __syncthreads();                        // stage c resident for all

        // ---- convert fp32 staging -> fp16 operand buffers ----
        {
            const float* stg = smem + (c & 1) * (STG_BYTES / 4);
            const __half* dummy = nullptr; (void)dummy;
            #pragma unroll
            for (int it = 0; it < 4; ++it) {    // A: 1024 quads
                const int q = tid + it * 256;
                const int r = q >> 3, kq = q & 7;
                float4 v = *reinterpret_cast<const float4*>(stg + r * BK + kq * 4);
                __half2 h0 = __floats2half2_rn(v.x, v.y);
                __half2 h1 = __floats2half2_rn(v.z, v.w);
                uint32_t u0 = *reinterpret_cast<uint32_t*>(&h0);
                uint32_t u1 = *reinterpret_cast<uint32_t*>(&h1);
                uint2 pk = make_uint2(u0, u1);
                *reinterpret_cast<uint2*>(
                    reinterpret_cast<char*>(smem) + FA_OFF + r * HROW + kq * 8) = pk;
            }
            const float* stgB = stg + STG_A_FLOATS;
            #pragma unroll
            for (int it = 0; it < 8; ++it) {    // B: 2048 quads
                const int q = tid + it * 256;
                const int r = q >> 3, kq = q & 7;
                float4 v = *reinterpret_cast<const float4*>(stgB + r * BK + kq * 4);
                __half2 h0 = __floats2half2_rn(v.x, v.y);
                __half2 h1 = __floats2half2_rn(v.z, v.w);
                uint32_t u0 = *reinterpret_cast<uint32_t*>(&h0);
                uint32_t u1 = *reinterpret_cast<uint32_t*>(&h1);
                uint2 pk = make_uint2(u0, u1);
                *reinterpret_cast<uint2*>(
                    reinterpret_cast<char*>(smem) + FB_OFF + r * HROW + kq * 8) = pk;
            }
        }
        __syncthreads();                        // fp16 ready; staging c free

        if (c + 2 < NCHUNK) issue_stage(c + 2);
        cp_commit();

        // ---- MMA: warp tile 64m x 64n x 32k ----
        #pragma unroll
        for (int k16 = 0; k16 < BK / 16; ++k16) {
            const int kc = k16 * 16 + koff;
            uint32_t af[4][4], bf[4][4];
            #pragma unroll
            for (int mt = 0; mt < 4; ++mt)
                ldsm4(af[mt], fa + (uint32_t)((wm * 64 + mt * 16 + rowoff) * HROW + kc * 2));
            #pragma unroll
            for (int nt = 0; nt < 4; ++nt)
                ldsm4(bf[nt], fb + (uint32_t)((wn * 64 + nt * 16 + rowoff) * HROW + kc * 2));
            #pragma unroll
            for (int mt = 0; mt < 4; ++mt)
                #pragma unroll
                for (int nt = 0; nt < 4; ++nt) {
                    mma16(acc[mt][nt * 2 + 0], af[mt][0], af[mt][1], af[mt][2], af[mt][3],
                          bf[nt][0], bf[nt][2]);
                    mma16(acc[mt][nt * 2 + 1], af[mt][0], af[mt][1], af[mt][2], af[mt][3],
                          bf[nt][1], bf[nt][3]);
                }
        }
    }

    // ---- epilogue ----
    const int g  = lid >> 2;
    const int tg = lid & 3;
    float* ob = out + (size_t)row0 * ROWSTRIDE + i * PDIM;
    #pragma unroll
    for (int mt = 0; mt < 4; ++mt) {
        #pragma unroll
        for (int nt = 0; nt < 8; ++nt) {
            const int r0 = wm * 64 + mt * 16 + g;
            const int cc = wn * 64 + nt * 8 + tg * 2;
            float2 v0 = make_float2(acc[mt][nt][0], acc[mt][nt][1]);
            float2 v1 = make_float2(acc[mt][nt][2], acc[mt][nt][3]);
            *reinterpret_cast<float2*>(ob + (size_t)r0 * ROWSTRIDE + cc) = v0;
            *reinterpret_cast<float2*>(ob + (size_t)(r0 + 8) * ROWSTRIDE + cc) = v1;
        }
    }
}

extern "C" void kernel_launch(void* const* d_in, const int* in_sizes, int n_in,
                              void* d_out, int out_size)
{
    const float* x   = (const float*)d_in[0];
    const float* Wd  = (const float*)d_in[1];
    const float* Wu  = (const float*)d_in[2];
    const float* Wl  = (const float*)d_in[3];
    const float* Wtr = (const float*)d_in[4];
    const float* Wbl = (const float*)d_in[5];
    float* out = (float*)d_out;

    cudaFuncSetAttribute(bxdiag_ldsm_kernel,
                         cudaFuncAttributeMaxDynamicSharedMemorySize, SMEM_BYTES);
    dim3 grid(BATCH / TILE_M, MBLK);   // 32 x 64 = 2048 CTAs
    bxdiag_ldsm_kernel<<<grid, 256, SMEM_BYTES>>>(x, Wd, Wu, Wl, Wtr, Wbl, out);
}

// round 6
// speedup vs baseline: 1.8091x; 1.1471x over previous
#include <cuda_runtime.h>
#include <cuda_fp16.h>
#include <cstdint>

#define MBLK 64
#define PDIM 256
#define BATCH 4096
#define ROWSTRIDE 16384            // floats/halves per batch row

#define TILE_M 128
#define TILE_N 256
#define BK 64                      // halves per chunk (128B rows)
#define NCHUNK 12                  // 3 segments * 256/64
#define NSTAGE 3

#define HROW 144                   // padded row stride bytes: (r*9+c)%8 covers banks
#define SA_BYTES (TILE_M * HROW)   // 18432
#define SB_BYTES (TILE_N * HROW)   // 36864
#define STAGE_BYTES (SA_BYTES + SB_BYTES)      // 55296
#define SMEM_BYTES (STAGE_BYTES * NSTAGE)      // 165888

// fp16 scratch (converted once per launch)
__device__ __half g_xh[(size_t)BATCH * ROWSTRIDE];        // 134 MB
__device__ __half g_wh[(size_t)192 * PDIM * PDIM];        // 25 MB
// g_wh block offsets (units of PDIM*PDIM): Wd 0..63, Wu 64..126, Wl 127..189, Wtr 190, Wbl 191

__device__ __forceinline__ uint32_t smem_u32(const void* p) {
    uint32_t a;
    asm("{ .reg .u64 t; cvta.to.shared.u64 t, %1; cvt.u32.u64 %0, t; }" : "=r"(a) : "l"(p));
    return a;
}
__device__ __forceinline__ void cp16(uint32_t dst, const void* src) {
    asm volatile("cp.async.cg.shared.global [%0], [%1], 16;\n" :: "r"(dst), "l"(src));
}
__device__ __forceinline__ void cp_commit() {
    asm volatile("cp.async.commit_group;\n" ::: "memory");
}
template <int N>
__device__ __forceinline__ void cp_wait() {
    asm volatile("cp.async.wait_group %0;\n" :: "n"(N) : "memory");
}
__device__ __forceinline__ void ldsm4(uint32_t* r, uint32_t addr) {
    asm volatile("ldmatrix.sync.aligned.m8n8.x4.shared.b16 {%0,%1,%2,%3}, [%4];\n"
                 : "=r"(r[0]), "=r"(r[1]), "=r"(r[2]), "=r"(r[3]) : "r"(addr));
}
__device__ __forceinline__ void mma16(float* c,
                                      uint32_t a0, uint32_t a1, uint32_t a2, uint32_t a3,
                                      uint32_t b0, uint32_t b1) {
    asm volatile(
        "mma.sync.aligned.m16n8k16.row.col.f32.f16.f16.f32 "
        "{%0,%1,%2,%3}, {%4,%5,%6,%7}, {%8,%9}, {%0,%1,%2,%3};\n"
        : "+f"(c[0]), "+f"(c[1]), "+f"(c[2]), "+f"(c[3])
        : "r"(a0), "r"(a1), "r"(a2), "r"(a3), "r"(b0), "r"(b1));
}

// ---------------- prologue converters ----------------
__global__ void __launch_bounds__(256) cvt_x_kernel(const float* __restrict__ src) {
    size_t i = ((size_t)blockIdx.x * 256 + threadIdx.x) * 8;
    float4 v0 = *reinterpret_cast<const float4*>(src + i);
    float4 v1 = *reinterpret_cast<const float4*>(src + i + 4);
    __half2 h[4] = { __floats2half2_rn(v0.x, v0.y), __floats2half2_rn(v0.z, v0.w),
                     __floats2half2_rn(v1.x, v1.y), __floats2half2_rn(v1.z, v1.w) };
    *reinterpret_cast<uint4*>(g_xh + i) = *reinterpret_cast<uint4*>(h);
}
__global__ void __launch_bounds__(256) cvt_w_kernel(const float* __restrict__ src, size_t dstoff) {
    size_t i = ((size_t)blockIdx.x * 256 + threadIdx.x) * 8;
    float4 v0 = *reinterpret_cast<const float4*>(src + i);
    float4 v1 = *reinterpret_cast<const float4*>(src + i + 4);
    __half2 h[4] = { __floats2half2_rn(v0.x, v0.y), __floats2half2_rn(v0.z, v0.w),
                     __floats2half2_rn(v1.x, v1.y), __floats2half2_rn(v1.z, v1.w) };
    *reinterpret_cast<uint4*>(g_wh + dstoff + i) = *reinterpret_cast<uint4*>(h);
}

// segment s of output block i -> (source block j, weight block index into g_wh)
__device__ __forceinline__ int seg_wblk(int s, int i, int& j) {
    if (s == 0) { j = i;            return i; }
    if (s == 1) { j = (i + 1) & 63; return (i < 63) ? 64 + i : 191; }
    j = (i + 63) & 63;              return (i > 0) ? 127 + (i - 1) : 190;
}

// ---------------- main GEMM ----------------
__global__ void __launch_bounds__(256, 1)
bxdiag_h16_kernel(float* __restrict__ out)
{
    extern __shared__ __align__(128) char smem[];
    const uint32_t sbase = smem_u32(smem);

    const int tid = threadIdx.x;
    const int wid = tid >> 5;
    const int lid = tid & 31;
    const int wm  = wid & 1;       // 64-row half
    const int wn  = wid >> 1;      // 64-col quarter
    const int bt  = blockIdx.x;
    const int i   = blockIdx.y;
    const int row0 = bt * TILE_M;

    auto issue_stage = [&](int c) {
        const int s  = c >> 2;                 // 0..2
        const int k0 = (c & 3) * BK;
        int j;
        const int wblk = seg_wblk(s, i, j);
        const __half* xsrc = g_xh + (size_t)row0 * ROWSTRIDE + j * PDIM + k0;
        const __half* wsrc = g_wh + (size_t)wblk * (PDIM * PDIM) + k0;
        const uint32_t ab = sbase + (uint32_t)((c % NSTAGE) * STAGE_BYTES);
        const uint32_t bb = ab + SA_BYTES;
        #pragma unroll
        for (int it = 0; it < 4; ++it) {       // A: 128 rows x 8 x 16B
            const int ch = tid + it * 256;
            const int r = ch >> 3, cc = ch & 7;
            cp16(ab + (uint32_t)(r * HROW + cc * 16),
                 xsrc + (size_t)r * ROWSTRIDE + cc * 8);
        }
        #pragma unroll
        for (int it = 0; it < 8; ++it) {       // B: 256 rows x 8 x 16B
            const int ch = tid + it * 256;
            const int r = ch >> 3, cc = ch & 7;
            cp16(bb + (uint32_t)(r * HROW + cc * 16),
                 wsrc + r * PDIM + cc * 8);
        }
    };

    float acc[4][8][4];
    #pragma unroll
    for (int mt = 0; mt < 4; ++mt)
        #pragma unroll
        for (int nt = 0; nt < 8; ++nt)
            #pragma unroll
            for (int q = 0; q < 4; ++q)
                acc[mt][nt][q] = 0.0f;

    issue_stage(0); cp_commit();
    issue_stage(1); cp_commit();

    const int sub    = lid >> 3;
    const int rowoff = ((sub & 1) << 3) + (lid & 7);
    const int koff   = (sub >> 1) << 3;        // 0 or 8 (halves)

    #pragma unroll 1
    for (int c = 0; c < NCHUNK; ++c) {
        cp_wait<1>();
        __syncthreads();                       // stage c resident; stage c-1 free

        if (c + 2 < NCHUNK) issue_stage(c + 2);
        cp_commit();

        const uint32_t fa = sbase + (uint32_t)((c % NSTAGE) * STAGE_BYTES);
        const uint32_t fb = fa + SA_BYTES;

        #pragma unroll
        for (int k16 = 0; k16 < BK / 16; ++k16) {
            const int kc = k16 * 16 + koff;
            uint32_t af[4][4], bf[4][4];
            #pragma unroll
            for (int mt = 0; mt < 4; ++mt)
                ldsm4(af[mt], fa + (uint32_t)((wm * 64 + mt * 16 + rowoff) * HROW + kc * 2));
            #pragma unroll
            for (int nt = 0; nt < 4; ++nt)
                ldsm4(bf[nt], fb + (uint32_t)((wn * 64 + nt * 16 + rowoff) * HROW + kc * 2));
            #pragma unroll
            for (int mt = 0; mt < 4; ++mt)
                #pragma unroll
                for (int nt = 0; nt < 4; ++nt) {
                    mma16(acc[mt][nt * 2 + 0], af[mt][0], af[mt][1], af[mt][2], af[mt][3],
                          bf[nt][0], bf[nt][2]);
                    mma16(acc[mt][nt * 2 + 1], af[mt][0], af[mt][1], af[mt][2], af[mt][3],
                          bf[nt][1], bf[nt][3]);
                }
        }
    }

    const int g  = lid >> 2;
    const int tg = lid & 3;
    float* ob = out + (size_t)row0 * ROWSTRIDE + i * PDIM;
    #pragma unroll
    for (int mt = 0; mt < 4; ++mt) {
        #pragma unroll
        for (int nt = 0; nt < 8; ++nt) {
            const int r0 = wm * 64 + mt * 16 + g;
            const int cc = wn * 64 + nt * 8 + tg * 2;
            float2 v0 = make_float2(acc[mt][nt][0], acc[mt][nt][1]);
            float2 v1 = make_float2(acc[mt][nt][2], acc[mt][nt][3]);
            *reinterpret_cast<float2*>(ob + (size_t)r0 * ROWSTRIDE + cc) = v0;
            *reinterpret_cast<float2*>(ob + (size_t)(r0 + 8) * ROWSTRIDE + cc) = v1;
        }
    }
}

extern "C" void kernel_launch(void* const* d_in, const int* in_sizes, int n_in,
                              void* d_out, int out_size)
{
    const float* x   = (const float*)d_in[0];
    const float* Wd  = (const float*)d_in[1];
    const float* Wu  = (const float*)d_in[2];
    const float* Wl  = (const float*)d_in[3];
    const float* Wtr = (const float*)d_in[4];
    const float* Wbl = (const float*)d_in[5];
    float* out = (float*)d_out;

    const size_t PB = (size_t)PDIM * PDIM;     // 65536
    // converts: 2048 halves per block (256 threads x 8)
    cvt_x_kernel<<<(unsigned)((size_t)BATCH * ROWSTRIDE / 2048), 256>>>(x);
    cvt_w_kernel<<<(unsigned)(64 * PB / 2048), 256>>>(Wd, 0);
    cvt_w_kernel<<<(unsigned)(63 * PB / 2048), 256>>>(Wu, 64 * PB);
    cvt_w_kernel<<<(unsigned)(63 * PB / 2048), 256>>>(Wl, 127 * PB);
    cvt_w_kernel<<<(unsigned)(PB / 2048), 256>>>(Wtr, 190 * PB);
    cvt_w_kernel<<<(unsigned)(PB / 2048), 256>>>(Wbl, 191 * PB);

    cudaFuncSetAttribute(bxdiag_h16_kernel,
                         cudaFuncAttributeMaxDynamicSharedMemorySize, SMEM_BYTES);
    dim3 grid(BATCH / TILE_M, MBLK);           // 32 x 64 = 2048 CTAs
    bxdiag_h16_kernel<<<grid, 256, SMEM_BYTES>>>(out);
}

// round 7
// speedup vs baseline: 1.8509x; 1.0231x over previous
#include <cuda_runtime.h>
#include <cuda_fp16.h>
#include <cstdint>

#define MBLK 64
#define PDIM 256
#define BATCH 4096
#define ROWSTRIDE 16384            // halves/floats per batch row

#define TILE_M 128
#define TILE_N 256
#define BK 64                      // halves per chunk (128B rows)
#define NCHUNK 12                  // 3 segments * 256/64
#define NSTAGE 3

#define HROW 144                   // padded row stride bytes
#define SA_BYTES (TILE_M * HROW)   // 18432
#define SB_BYTES (TILE_N * HROW)   // 36864
#define STAGE_BYTES (SA_BYTES + SB_BYTES)      // 55296
#define SMEM_BYTES (STAGE_BYTES * NSTAGE)      // 165888

__device__ __half g_xh[(size_t)BATCH * ROWSTRIDE];        // 134 MB
__device__ __half g_wh[(size_t)192 * PDIM * PDIM];        // 25 MB

__device__ __forceinline__ uint32_t smem_u32(const void* p) {
    uint32_t a;
    asm("{ .reg .u64 t; cvta.to.shared.u64 t, %1; cvt.u32.u64 %0, t; }" : "=r"(a) : "l"(p));
    return a;
}
__device__ __forceinline__ void cp16(uint32_t dst, const void* src) {
    asm volatile("cp.async.cg.shared.global [%0], [%1], 16;\n" :: "r"(dst), "l"(src));
}
__device__ __forceinline__ void cp_commit() {
    asm volatile("cp.async.commit_group;\n" ::: "memory");
}
template <int N>
__device__ __forceinline__ void cp_wait() {
    asm volatile("cp.async.wait_group %0;\n" :: "n"(N) : "memory");
}
__device__ __forceinline__ void ldsm4(uint32_t* r, uint32_t addr) {
    asm volatile("ldmatrix.sync.aligned.m8n8.x4.shared.b16 {%0,%1,%2,%3}, [%4];\n"
                 : "=r"(r[0]), "=r"(r[1]), "=r"(r[2]), "=r"(r[3]) : "r"(addr));
}
__device__ __forceinline__ void mma16(float* c,
                                      uint32_t a0, uint32_t a1, uint32_t a2, uint32_t a3,
                                      uint32_t b0, uint32_t b1) {
    asm volatile(
        "mma.sync.aligned.m16n8k16.row.col.f32.f16.f16.f32 "
        "{%0,%1,%2,%3}, {%4,%5,%6,%7}, {%8,%9}, {%0,%1,%2,%3};\n"
        : "+f"(c[0]), "+f"(c[1]), "+f"(c[2]), "+f"(c[3])
        : "r"(a0), "r"(a1), "r"(a2), "r"(a3), "r"(b0), "r"(b1));
}

// ---------------- prologue converters ----------------
__global__ void __launch_bounds__(256) cvt_x_kernel(const float* __restrict__ src) {
    size_t i = ((size_t)blockIdx.x * 256 + threadIdx.x) * 8;
    float4 v0 = *reinterpret_cast<const float4*>(src + i);
    float4 v1 = *reinterpret_cast<const float4*>(src + i + 4);
    __half2 h[4] = { __floats2half2_rn(v0.x, v0.y), __floats2half2_rn(v0.z, v0.w),
                     __floats2half2_rn(v1.x, v1.y), __floats2half2_rn(v1.z, v1.w) };
    *reinterpret_cast<uint4*>(g_xh + i) = *reinterpret_cast<uint4*>(h);
}
__global__ void __launch_bounds__(256) cvt_w_kernel(const float* __restrict__ src, size_t dstoff) {
    size_t i = ((size_t)blockIdx.x * 256 + threadIdx.x) * 8;
    float4 v0 = *reinterpret_cast<const float4*>(src + i);
    float4 v1 = *reinterpret_cast<const float4*>(src + i + 4);
    __half2 h[4] = { __floats2half2_rn(v0.x, v0.y), __floats2half2_rn(v0.z, v0.w),
                     __floats2half2_rn(v1.x, v1.y), __floats2half2_rn(v1.z, v1.w) };
    *reinterpret_cast<uint4*>(g_wh + dstoff + i) = *reinterpret_cast<uint4*>(h);
}

__device__ __forceinline__ int seg_wblk(int s, int i, int& j) {
    if (s == 0) { j = i;            return i; }
    if (s == 1) { j = (i + 1) & 63; return (i < 63) ? 64 + i : 191; }
    j = (i + 63) & 63;              return (i > 0) ? 127 + (i - 1) : 190;
}

// ---------------- main GEMM: 512 threads, warp grid 4(m) x 4(n) ----------------
__global__ void __launch_bounds__(512, 1)
bxdiag_h16_kernel(float* __restrict__ out)
{
    extern __shared__ __align__(128) char smem[];
    const uint32_t sbase = smem_u32(smem);

    const int tid = threadIdx.x;
    const int wid = tid >> 5;
    const int lid = tid & 31;
    const int wm  = wid & 3;       // 0..3 : 32-row quarter
    const int wn  = wid >> 2;      // 0..3 : 64-col quarter
    const int bt  = blockIdx.x;
    const int i   = blockIdx.y;
    const int row0 = bt * TILE_M;

    auto issue_stage = [&](int c) {
        const int s  = c >> 2;
        const int k0 = (c & 3) * BK;
        int j;
        const int wblk = seg_wblk(s, i, j);
        const __half* xsrc = g_xh + (size_t)row0 * ROWSTRIDE + j * PDIM + k0;
        const __half* wsrc = g_wh + (size_t)wblk * (PDIM * PDIM) + k0;
        const uint32_t ab = sbase + (uint32_t)((c % NSTAGE) * STAGE_BYTES);
        const uint32_t bb = ab + SA_BYTES;
        #pragma unroll
        for (int it = 0; it < 2; ++it) {       // A: 128 rows x 8 x 16B = 1024
            const int ch = tid + it * 512;
            const int r = ch >> 3, cc = ch & 7;
            cp16(ab + (uint32_t)(r * HROW + cc * 16),
                 xsrc + (size_t)r * ROWSTRIDE + cc * 8);
        }
        #pragma unroll
        for (int it = 0; it < 4; ++it) {       // B: 256 rows x 8 x 16B = 2048
            const int ch = tid + it * 512;
            const int r = ch >> 3, cc = ch & 7;
            cp16(bb + (uint32_t)(r * HROW + cc * 16),
                 wsrc + r * PDIM + cc * 8);
        }
    };

    float acc[2][8][4];
    #pragma unroll
    for (int mt = 0; mt < 2; ++mt)
        #pragma unroll
        for (int nt = 0; nt < 8; ++nt)
            #pragma unroll
            for (int q = 0; q < 4; ++q)
                acc[mt][nt][q] = 0.0f;

    issue_stage(0); cp_commit();
    issue_stage(1); cp_commit();

    const int sub    = lid >> 3;
    const int rowoff = ((sub & 1) << 3) + (lid & 7);
    const int koff   = (sub >> 1) << 3;        // 0 or 8 halves

    #pragma unroll 1
    for (int c = 0; c < NCHUNK; ++c) {
        cp_wait<1>();
        __syncthreads();                       // stage c resident

        if (c + 2 < NCHUNK) issue_stage(c + 2);
        cp_commit();

        const uint32_t fa = sbase + (uint32_t)((c % NSTAGE) * STAGE_BYTES);
        const uint32_t fb = fa + SA_BYTES;

        #pragma unroll
        for (int k16 = 0; k16 < BK / 16; ++k16) {
            const int kc = k16 * 16 + koff;
            uint32_t af[2][4], bf[4][4];
            #pragma unroll
            for (int mt = 0; mt < 2; ++mt)
                ldsm4(af[mt], fa + (uint32_t)((wm * 32 + mt * 16 + rowoff) * HROW + kc * 2));
            #pragma unroll
            for (int nt = 0; nt < 4; ++nt)
                ldsm4(bf[nt], fb + (uint32_t)((wn * 64 + nt * 16 + rowoff) * HROW + kc * 2));
            #pragma unroll
            for (int mt = 0; mt < 2; ++mt)
                #pragma unroll
                for (int nt = 0; nt < 4; ++nt) {
                    mma16(acc[mt][nt * 2 + 0], af[mt][0], af[mt][1], af[mt][2], af[mt][3],
                          bf[nt][0], bf[nt][2]);
                    mma16(acc[mt][nt * 2 + 1], af[mt][0], af[mt][1], af[mt][2], af[mt][3],
                          bf[nt][1], bf[nt][3]);
                }
        }
    }

    const int g  = lid >> 2;
    const int tg = lid & 3;
    float* ob = out + (size_t)row0 * ROWSTRIDE + i * PDIM;
    #pragma unroll
    for (int mt = 0; mt < 2; ++mt) {
        #pragma unroll
        for (int nt = 0; nt < 8; ++nt) {
            const int r0 = wm * 32 + mt * 16 + g;
            const int cc = wn * 64 + nt * 8 + tg * 2;
            float2 v0 = make_float2(acc[mt][nt][0], acc[mt][nt][1]);
            float2 v1 = make_float2(acc[mt][nt][2], acc[mt][nt][3]);
            *reinterpret_cast<float2*>(ob + (size_t)r0 * ROWSTRIDE + cc) = v0;
            *reinterpret_cast<float2*>(ob + (size_t)(r0 + 8) * ROWSTRIDE + cc) = v1;
        }
    }
}

extern "C" void kernel_launch(void* const* d_in, const int* in_sizes, int n_in,
                              void* d_out, int out_size)
{
    const float* x   = (const float*)d_in[0];
    const float* Wd  = (const float*)d_in[1];
    const float* Wu  = (const float*)d_in[2];
    const float* Wl  = (const float*)d_in[3];
    const float* Wtr = (const float*)d_in[4];
    const float* Wbl = (const float*)d_in[5];
    float* out = (float*)d_out;

    const size_t PB = (size_t)PDIM * PDIM;
    cvt_x_kernel<<<(unsigned)((size_t)BATCH * ROWSTRIDE / 2048), 256>>>(x);
    cvt_w_kernel<<<(unsigned)(64 * PB / 2048), 256>>>(Wd, 0);
    cvt_w_kernel<<<(unsigned)(63 * PB / 2048), 256>>>(Wu, 64 * PB);
    cvt_w_kernel<<<(unsigned)(63 * PB / 2048), 256>>>(Wl, 127 * PB);
    cvt_w_kernel<<<(unsigned)(PB / 2048), 256>>>(Wtr, 190 * PB);
    cvt_w_kernel<<<(unsigned)(PB / 2048), 256>>>(Wbl, 191 * PB);

    cudaFuncSetAttribute(bxdiag_h16_kernel,
                         cudaFuncAttributeMaxDynamicSharedMemorySize, SMEM_BYTES);
    dim3 grid(BATCH / TILE_M, MBLK);           // 32 x 64 = 2048 CTAs
    bxdiag_h16_kernel<<<grid, 512, SMEM_BYTES>>>(out);
}

// round 8
// speedup vs baseline: 1.9226x; 1.0387x over previous
#include <cuda_runtime.h>
#include <cuda_fp16.h>
#include <cstdint>

#define MBLK 64
#define PDIM 256
#define BATCH 4096
#define ROWSTRIDE 16384            // halves/floats per batch row

#define TILE_M 64
#define TILE_N 256
#define BK 64                      // halves per chunk
#define NCHUNK 12                  // 3 segments * 256/64
#define NSTAGE 2

#define HROW 144                   // padded row stride bytes
#define SA_BYTES (TILE_M * HROW)   // 9216
#define SB_BYTES (TILE_N * HROW)   // 36864
#define STAGE_BYTES (SA_BYTES + SB_BYTES)   // 46080
#define SMEM_BYTES (STAGE_BYTES * NSTAGE)   // 92160  -> 2 CTAs/SM

__device__ __half g_xh[(size_t)BATCH * ROWSTRIDE];        // 134 MB
__device__ __half g_wh[(size_t)192 * PDIM * PDIM];        // 25 MB

__device__ __forceinline__ uint32_t smem_u32(const void* p) {
    uint32_t a;
    asm("{ .reg .u64 t; cvta.to.shared.u64 t, %1; cvt.u32.u64 %0, t; }" : "=r"(a) : "l"(p));
    return a;
}
__device__ __forceinline__ void cp16(uint32_t dst, const void* src) {
    asm volatile("cp.async.cg.shared.global [%0], [%1], 16;\n" :: "r"(dst), "l"(src));
}
__device__ __forceinline__ void cp_commit() {
    asm volatile("cp.async.commit_group;\n" ::: "memory");
}
template <int N>
__device__ __forceinline__ void cp_wait() {
    asm volatile("cp.async.wait_group %0;\n" :: "n"(N) : "memory");
}
__device__ __forceinline__ void ldsm4(uint32_t* r, uint32_t addr) {
    asm volatile("ldmatrix.sync.aligned.m8n8.x4.shared.b16 {%0,%1,%2,%3}, [%4];\n"
                 : "=r"(r[0]), "=r"(r[1]), "=r"(r[2]), "=r"(r[3]) : "r"(addr));
}
__device__ __forceinline__ void mma16(float* c,
                                      uint32_t a0, uint32_t a1, uint32_t a2, uint32_t a3,
                                      uint32_t b0, uint32_t b1) {
    asm volatile(
        "mma.sync.aligned.m16n8k16.row.col.f32.f16.f16.f32 "
        "{%0,%1,%2,%3}, {%4,%5,%6,%7}, {%8,%9}, {%0,%1,%2,%3};\n"
        : "+f"(c[0]), "+f"(c[1]), "+f"(c[2]), "+f"(c[3])
        : "r"(a0), "r"(a1), "r"(a2), "r"(a3), "r"(b0), "r"(b1));
}

// ---------------- prologue converters ----------------
__global__ void __launch_bounds__(256) cvt_x_kernel(const float* __restrict__ src) {
    size_t i = ((size_t)blockIdx.x * 256 + threadIdx.x) * 8;
    float4 v0 = *reinterpret_cast<const float4*>(src + i);
    float4 v1 = *reinterpret_cast<const float4*>(src + i + 4);
    __half2 h[4] = { __floats2half2_rn(v0.x, v0.y), __floats2half2_rn(v0.z, v0.w),
                     __floats2half2_rn(v1.x, v1.y), __floats2half2_rn(v1.z, v1.w) };
    *reinterpret_cast<uint4*>(g_xh + i) = *reinterpret_cast<uint4*>(h);
}
__global__ void __launch_bounds__(256) cvt_w_kernel(const float* __restrict__ src, size_t dstoff) {
    size_t i = ((size_t)blockIdx.x * 256 + threadIdx.x) * 8;
    float4 v0 = *reinterpret_cast<const float4*>(src + i);
    float4 v1 = *reinterpret_cast<const float4*>(src + i + 4);
    __half2 h[4] = { __floats2half2_rn(v0.x, v0.y), __floats2half2_rn(v0.z, v0.w),
                     __floats2half2_rn(v1.x, v1.y), __floats2half2_rn(v1.z, v1.w) };
    *reinterpret_cast<uint4*>(g_wh + dstoff + i) = *reinterpret_cast<uint4*>(h);
}

__device__ __forceinline__ int seg_wblk(int s, int i, int& j) {
    if (s == 0) { j = i;            return i; }
    if (s == 1) { j = (i + 1) & 63; return (i < 63) ? 64 + i : 191; }
    j = (i + 63) & 63;              return (i > 0) ? 127 + (i - 1) : 190;
}

// ---------------- main GEMM: 256 threads, 2 CTAs/SM ----------------
__global__ void __launch_bounds__(256, 2)
bxdiag_h16_kernel(float* __restrict__ out)
{
    extern __shared__ __align__(128) char smem[];
    const uint32_t sbase = smem_u32(smem);

    const int tid = threadIdx.x;
    const int wid = tid >> 5;
    const int lid = tid & 31;
    const int wm  = wid & 1;       // 0..1 : 32-row half
    const int wn  = wid >> 1;      // 0..3 : 64-col quarter
    const int bt  = blockIdx.x;    // batch tile 0..63
    const int i   = blockIdx.y;    // output block 0..63
    const int row0 = bt * TILE_M;

    auto issue_stage = [&](int c) {
        const int s  = c >> 2;
        const int k0 = (c & 3) * BK;
        int j;
        const int wblk = seg_wblk(s, i, j);
        const __half* xsrc = g_xh + (size_t)row0 * ROWSTRIDE + j * PDIM + k0;
        const __half* wsrc = g_wh + (size_t)wblk * (PDIM * PDIM) + k0;
        const uint32_t ab = sbase + (uint32_t)((c & 1) * STAGE_BYTES);
        const uint32_t bb = ab + SA_BYTES;
        {   // A: 64 rows x 8 x 16B = 512 -> 2 per thread
            #pragma unroll
            for (int it = 0; it < 2; ++it) {
                const int ch = tid + it * 256;
                const int r = ch >> 3, cc = ch & 7;
                cp16(ab + (uint32_t)(r * HROW + cc * 16),
                     xsrc + (size_t)r * ROWSTRIDE + cc * 8);
            }
        }
        #pragma unroll
        for (int it = 0; it < 8; ++it) {       // B: 256 rows x 8 x 16B = 2048
            const int ch = tid + it * 256;
            const int r = ch >> 3, cc = ch & 7;
            cp16(bb + (uint32_t)(r * HROW + cc * 16),
                 wsrc + r * PDIM + cc * 8);
        }
    };

    float acc[2][8][4];
    #pragma unroll
    for (int mt = 0; mt < 2; ++mt)
        #pragma unroll
        for (int nt = 0; nt < 8; ++nt)
            #pragma unroll
            for (int q = 0; q < 4; ++q)
                acc[mt][nt][q] = 0.0f;

    issue_stage(0); cp_commit();
    issue_stage(1); cp_commit();

    const int sub    = lid >> 3;
    const int rowoff = ((sub & 1) << 3) + (lid & 7);
    const int koff   = (sub >> 1) << 3;        // 0 or 8 halves

    #pragma unroll 1
    for (int c = 0; c < NCHUNK; ++c) {
        cp_wait<1>();
        __syncthreads();                       // stage c resident

        const uint32_t fa = sbase + (uint32_t)((c & 1) * STAGE_BYTES);
        const uint32_t fb = fa + SA_BYTES;

        #pragma unroll
        for (int k16 = 0; k16 < BK / 16; ++k16) {
            const int kc = k16 * 16 + koff;
            uint32_t af[2][4], bf[4][4];
            #pragma unroll
            for (int mt = 0; mt < 2; ++mt)
                ldsm4(af[mt], fa + (uint32_t)((wm * 32 + mt * 16 + rowoff) * HROW + kc * 2));
            #pragma unroll
            for (int nt = 0; nt < 4; ++nt)
                ldsm4(bf[nt], fb + (uint32_t)((wn * 64 + nt * 16 + rowoff) * HROW + kc * 2));
            #pragma unroll
            for (int mt = 0; mt < 2; ++mt)
                #pragma unroll
                for (int nt = 0; nt < 4; ++nt) {
                    mma16(acc[mt][nt * 2 + 0], af[mt][0], af[mt][1], af[mt][2], af[mt][3],
                          bf[nt][0], bf[nt][2]);
                    mma16(acc[mt][nt * 2 + 1], af[mt][0], af[mt][1], af[mt][2], af[mt][3],
                          bf[nt][1], bf[nt][3]);
                }
        }

        __syncthreads();                       // buffer (c&1) free for reuse
        if (c + 2 < NCHUNK) issue_stage(c + 2);
        cp_commit();
    }

    const int g  = lid >> 2;
    const int tg = lid & 3;
    float* ob = out + (size_t)row0 * ROWSTRIDE + i * PDIM;
    #pragma unroll
    for (int mt = 0; mt < 2; ++mt) {
        #pragma unroll
        for (int nt = 0; nt < 8; ++nt) {
            const int r0 = wm * 32 + mt * 16 + g;
            const int cc = wn * 64 + nt * 8 + tg * 2;
            float2 v0 = make_float2(acc[mt][nt][0], acc[mt][nt][1]);
            float2 v1 = make_float2(acc[mt][nt][2], acc[mt][nt][3]);
            *reinterpret_cast<float2*>(ob + (size_t)r0 * ROWSTRIDE + cc) = v0;
            *reinterpret_cast<float2*>(ob + (size_t)(r0 + 8) * ROWSTRIDE + cc) = v1;
        }
    }
}

extern "C" void kernel_launch(void* const* d_in, const int* in_sizes, int n_in,
                              void* d_out, int out_size)
{
    const float* x   = (const float*)d_in[0];
    const float* Wd  = (const float*)d_in[1];
    const float* Wu  = (const float*)d_in[2];
    const float* Wl  = (const float*)d_in[3];
    const float* Wtr = (const float*)d_in[4];
    const float* Wbl = (const float*)d_in[5];
    float* out = (float*)d_out;

    const size_t PB = (size_t)PDIM * PDIM;
    cvt_x_kernel<<<(unsigned)((size_t)BATCH * ROWSTRIDE / 2048), 256>>>(x);
    cvt_w_kernel<<<(unsigned)(64 * PB / 2048), 256>>>(Wd, 0);
    cvt_w_kernel<<<(unsigned)(63 * PB / 2048), 256>>>(Wu, 64 * PB);
    cvt_w_kernel<<<(unsigned)(63 * PB / 2048), 256>>>(Wl, 127 * PB);
    cvt_w_kernel<<<(unsigned)(PB / 2048), 256>>>(Wtr, 190 * PB);
    cvt_w_kernel<<<(unsigned)(PB / 2048), 256>>>(Wbl, 191 * PB);

    cudaFuncSetAttribute(bxdiag_h16_kernel,
                         cudaFuncAttributeMaxDynamicSharedMemorySize, SMEM_BYTES);
    dim3 grid(BATCH / TILE_M, MBLK);           // 64 x 64 = 4096 CTAs
    bxdiag_h16_kernel<<<grid, 256, SMEM_BYTES>>>(out);
}